// round 1
// baseline (speedup 1.0000x reference)
#include <cuda_runtime.h>
#include <cstdint>

// ---------------- constants ----------------
#define BB 8
#define NN 8192
#define DD 512
#define HH 8
#define MM 64
// HD = 64, H*M = 512

// ---------------- device scratch (no allocs allowed) ----------------
__device__ float g_kv[67108864];        // [B,N,2D]  256MB
__device__ float g_scores[33554432];    // [B,512,N] 128MB
__device__ float g_mixed[33554432];     // [B,512,N] 128MB (becomes slice_w in place)
__device__ float g_sumw[4096];          // [B,512]
__device__ float g_part[4194304];       // [64 bh][16 splits][64*64]
__device__ float g_stok[262144];        // [B,H,M,HD]
__device__ float g_st[262144];          // [B,M,D]
__device__ float g_qkv[786432];         // [B*M, 1536]
__device__ float g_otok[262144];        // [B,H,M,HD]
__device__ float g_pre[33554432];       // [B,N,D] 128MB

// ---------------- generic tiled SGEMM: C = A[M,K] @ B[K,N] (+bias) ----------------
// 128x128 tile, BK=16, 256 threads, 8x8 per thread. All dims multiples of tile.
__global__ __launch_bounds__(256)
void sgemm_kernel(const float* __restrict__ A, const float* __restrict__ Bm,
                  const float* __restrict__ bias, float* __restrict__ C,
                  int Mdim, int Ndim, int Kdim,
                  long long Abs, long long Bbs, long long Cbs)
{
    const int bz = blockIdx.z;
    A  += bz * Abs;
    Bm += bz * Bbs;
    C  += bz * Cbs;

    __shared__ float Asm[16][128];
    __shared__ float Bsm[16][128];

    const int tid = threadIdx.x;
    const int tx = tid & 15, ty = tid >> 4;
    const int m0 = blockIdx.y * 128, n0 = blockIdx.x * 128;

    float acc[8][8];
#pragma unroll
    for (int i = 0; i < 8; i++)
#pragma unroll
        for (int j = 0; j < 8; j++) acc[i][j] = 0.f;

    for (int kt = 0; kt < Kdim; kt += 16) {
#pragma unroll
        for (int i = 0; i < 2; i++) {
            int idx = tid + i * 256;            // 0..511
            int r = idx >> 2;                   // 0..127
            int c4 = idx & 3;                   // 0..3
            float4 v = *(const float4*)&A[(long long)(m0 + r) * Kdim + kt + c4 * 4];
            Asm[c4 * 4 + 0][r] = v.x;
            Asm[c4 * 4 + 1][r] = v.y;
            Asm[c4 * 4 + 2][r] = v.z;
            Asm[c4 * 4 + 3][r] = v.w;
        }
#pragma unroll
        for (int i = 0; i < 2; i++) {
            int idx = tid + i * 256;
            int r = idx >> 5;                   // 0..15
            int c4 = idx & 31;                  // 0..31
            *(float4*)&Bsm[r][c4 * 4] =
                *(const float4*)&Bm[(long long)(kt + r) * Ndim + n0 + c4 * 4];
        }
        __syncthreads();
#pragma unroll
        for (int k = 0; k < 16; k++) {
            float4 a0 = *(float4*)&Asm[k][ty * 8];
            float4 a1 = *(float4*)&Asm[k][ty * 8 + 4];
            float4 b0 = *(float4*)&Bsm[k][tx * 8];
            float4 b1 = *(float4*)&Bsm[k][tx * 8 + 4];
            float ra[8] = {a0.x, a0.y, a0.z, a0.w, a1.x, a1.y, a1.z, a1.w};
            float rb[8] = {b0.x, b0.y, b0.z, b0.w, b1.x, b1.y, b1.z, b1.w};
#pragma unroll
            for (int i = 0; i < 8; i++)
#pragma unroll
                for (int j = 0; j < 8; j++) acc[i][j] += ra[i] * rb[j];
        }
        __syncthreads();
    }

#pragma unroll
    for (int i = 0; i < 8; i++) {
        long long row = m0 + ty * 8 + i;
#pragma unroll
        for (int j = 0; j < 8; j += 4) {
            int col = n0 + tx * 8 + j;
            float4 v;
            v.x = acc[i][j + 0]; v.y = acc[i][j + 1];
            v.z = acc[i][j + 2]; v.w = acc[i][j + 3];
            if (bias) {
                v.x += bias[col + 0]; v.y += bias[col + 1];
                v.z += bias[col + 2]; v.w += bias[col + 3];
            }
            *(float4*)&C[row * Ndim + col] = v;
        }
    }
}

// ---------------- scores[b,h*64+m,n] = sum_d wtq[h,m,d] * xk[b,h,n,d] ----------------
// xk[b,h,n,d] = kv[(b*N+n)*1024 + h*64 + d]
__global__ __launch_bounds__(256)
void scores_kernel(const float* __restrict__ kv, const float* __restrict__ wtq,
                   float* __restrict__ scores)
{
    int bh = blockIdx.y; int b = bh >> 3, h = bh & 7;
    int n0 = blockIdx.x * 64;
    __shared__ float wts[64][68];   // [m][d]
    __shared__ float xs[64][68];    // [n][d]
    int tid = threadIdx.x;

    const float* wq = wtq + (long long)h * 4096;
#pragma unroll
    for (int i = 0; i < 4; i++) {
        int idx = tid + i * 256;    // 0..1023
        int m = idx >> 4, c4 = idx & 15;
        *(float4*)&wts[m][c4 * 4] = *(const float4*)&wq[m * 64 + c4 * 4];
    }
    const float* xk = kv + (long long)b * NN * 1024 + h * 64;
#pragma unroll
    for (int i = 0; i < 4; i++) {
        int idx = tid + i * 256;
        int n = idx >> 4, c4 = idx & 15;
        *(float4*)&xs[n][c4 * 4] = *(const float4*)&xk[(long long)(n0 + n) * 1024 + c4 * 4];
    }
    __syncthreads();

    int tx = tid & 15, ty = tid >> 4;  // tx->n(4), ty->m(4)
    float acc[4][4];
#pragma unroll
    for (int i = 0; i < 4; i++)
#pragma unroll
        for (int j = 0; j < 4; j++) acc[i][j] = 0.f;

#pragma unroll
    for (int d = 0; d < 64; d += 4) {
        float4 ra[4], rb[4];
#pragma unroll
        for (int i = 0; i < 4; i++) ra[i] = *(float4*)&wts[ty * 4 + i][d];
#pragma unroll
        for (int j = 0; j < 4; j++) rb[j] = *(float4*)&xs[tx * 4 + j][d];
#pragma unroll
        for (int i = 0; i < 4; i++)
#pragma unroll
            for (int j = 0; j < 4; j++)
                acc[i][j] += ra[i].x * rb[j].x + ra[i].y * rb[j].y +
                             ra[i].z * rb[j].z + ra[i].w * rb[j].w;
    }
    float* sc = scores + ((long long)b * 512 + h * 64) * NN + n0;
#pragma unroll
    for (int i = 0; i < 4; i++) {
        float4 v = {acc[i][0], acc[i][1], acc[i][2], acc[i][3]};
        *(float4*)&sc[(long long)(ty * 4 + i) * NN + tx * 4] = v;
    }
}

// ---------------- softmax over m (64 values, stride N) ----------------
__global__ __launch_bounds__(256)
void softmax_kernel(float* __restrict__ sc)
{
    int bh = blockIdx.y; int b = bh >> 3, h = bh & 7;
    int n = blockIdx.x * 256 + threadIdx.x;
    float* p = sc + ((long long)b * 512 + h * 64) * NN + n;
    float v[64];
#pragma unroll
    for (int m = 0; m < 64; m++) v[m] = p[(long long)m * NN];
    float mx = v[0];
#pragma unroll
    for (int m = 1; m < 64; m++) mx = fmaxf(mx, v[m]);
    float s = 0.f;
#pragma unroll
    for (int m = 0; m < 64; m++) { v[m] = __expf(v[m] - mx); s += v[m]; }
    float inv = 1.0f / s;
#pragma unroll
    for (int m = 0; m < 64; m++) p[(long long)m * NN] = v[m] * inv;
}

// ---------------- sumw[b*512+c] = sum_n slice_w[b,c,n] ----------------
__global__ __launch_bounds__(256)
void sumw_kernel(const float* __restrict__ sw, float* __restrict__ sumw)
{
    int bc = blockIdx.x;
    const float* p = sw + (long long)bc * NN;
    float s = 0.f;
    for (int n = threadIdx.x; n < NN; n += 256) s += p[n];
    __shared__ float red[256];
    red[threadIdx.x] = s; __syncthreads();
    for (int off = 128; off > 0; off >>= 1) {
        if (threadIdx.x < off) red[threadIdx.x] += red[threadIdx.x + off];
        __syncthreads();
    }
    if (threadIdx.x == 0) sumw[bc] = red[0];
}

// ---------------- slice_tok partials: deterministic split-K over n ----------------
// part[bh][split][m*64+d] = sum_{n in split} slice_w[b,h*64+m,n] * xv[b,h,n,d]
__global__ __launch_bounds__(256)
void stok_part_kernel(const float* __restrict__ sw, const float* __restrict__ kv,
                      float* __restrict__ part)
{
    int bh = blockIdx.y; int b = bh >> 3, h = bh & 7;
    int split = blockIdx.x;                 // 0..15, each covers 512 n
    __shared__ float sws[64][68];           // [m][n]
    __shared__ float xvs[64][64];           // [n][d]
    int tid = threadIdx.x;
    int tx = tid & 15, ty = tid >> 4;       // tx->d(4), ty->m(4)

    float acc[4][4];
#pragma unroll
    for (int i = 0; i < 4; i++)
#pragma unroll
        for (int j = 0; j < 4; j++) acc[i][j] = 0.f;

    const float* swb = sw + ((long long)b * 512 + h * 64) * NN;
    const float* xvb = kv + (long long)b * NN * 1024 + 512 + h * 64;

    for (int c = 0; c < 8; c++) {
        int n0 = split * 512 + c * 64;
#pragma unroll
        for (int i = 0; i < 4; i++) {
            int idx = tid + i * 256;
            int m = idx >> 4, c4 = idx & 15;
            *(float4*)&sws[m][c4 * 4] = *(const float4*)&swb[(long long)m * NN + n0 + c4 * 4];
        }
#pragma unroll
        for (int i = 0; i < 4; i++) {
            int idx = tid + i * 256;
            int n = idx >> 4, c4 = idx & 15;
            *(float4*)&xvs[n][c4 * 4] = *(const float4*)&xvb[(long long)(n0 + n) * 1024 + c4 * 4];
        }
        __syncthreads();
#pragma unroll 4
        for (int n = 0; n < 64; n++) {
            float rm[4];
#pragma unroll
            for (int i = 0; i < 4; i++) rm[i] = sws[ty * 4 + i][n];
            float4 rd = *(float4*)&xvs[n][tx * 4];
#pragma unroll
            for (int i = 0; i < 4; i++) {
                acc[i][0] += rm[i] * rd.x; acc[i][1] += rm[i] * rd.y;
                acc[i][2] += rm[i] * rd.z; acc[i][3] += rm[i] * rd.w;
            }
        }
        __syncthreads();
    }
    float* pp = part + ((long long)bh * 16 + split) * 4096;
#pragma unroll
    for (int i = 0; i < 4; i++) {
        float4 v = {acc[i][0], acc[i][1], acc[i][2], acc[i][3]};
        *(float4*)&pp[(ty * 4 + i) * 64 + tx * 4] = v;
    }
}

__global__ __launch_bounds__(256)
void stok_reduce_kernel(const float* __restrict__ part, float* __restrict__ stok)
{
    int bh = blockIdx.x;
    for (int i = threadIdx.x; i < 4096; i += 256) {
        float s = 0.f;
#pragma unroll
        for (int sp = 0; sp < 16; sp++) s += part[((long long)bh * 16 + sp) * 4096 + i];
        stok[(long long)bh * 4096 + i] = s;
    }
}

// ---------------- normalize by sumw + layernorm -> st[b,m,h*64+d] ----------------
__global__ __launch_bounds__(256)
void ln_kernel(const float* __restrict__ stok, const float* __restrict__ sumw,
               const float* __restrict__ gg, const float* __restrict__ bta,
               float* __restrict__ st)
{
    int warp = (blockIdx.x * blockDim.x + threadIdx.x) >> 5;  // 0..4095 = bh*64+m
    int lane = threadIdx.x & 31;
    int m = warp & 63, h = (warp >> 6) & 7, b = warp >> 9;

    float inv = 1.0f / (sumw[warp] + 1e-5f);
    const float* sp = stok + (long long)warp * 64;
    float x0 = sp[lane] * inv, x1 = sp[lane + 32] * inv;
    float s = x0 + x1;
#pragma unroll
    for (int o = 16; o; o >>= 1) s += __shfl_xor_sync(0xffffffffu, s, o);
    float mu = s * (1.0f / 64.0f);
    float d0 = x0 - mu, d1 = x1 - mu;
    float vs = d0 * d0 + d1 * d1;
#pragma unroll
    for (int o = 16; o; o >>= 1) vs += __shfl_xor_sync(0xffffffffu, vs, o);
    float rstd = rsqrtf(vs * (1.0f / 64.0f) + 1e-5f);
    float y0 = d0 * rstd * gg[lane] + bta[lane];
    float y1 = d1 * rstd * gg[lane + 32] + bta[lane + 32];
    float* op = st + ((long long)(b * 64 + m)) * 512 + h * 64;
    op[lane] = y0; op[lane + 32] = y1;
}

// ---------------- mini self-attention over M=64 tokens, one block per (b,h) ----------------
__global__ __launch_bounds__(256)
void attn_kernel(const float* __restrict__ qkv, float* __restrict__ otok)
{
    int bh = blockIdx.x; int b = bh >> 3, h = bh & 7;
    __shared__ float qs[64][68];
    __shared__ float ks[64][68];
    int tid = threadIdx.x;
    const float* base = qkv + (long long)b * 64 * 1536 + h * 64;

#pragma unroll
    for (int i = 0; i < 4; i++) {
        int idx = tid + i * 256;
        int m = idx >> 4, c4 = idx & 15;
        *(float4*)&qs[m][c4 * 4] = *(const float4*)&base[(long long)m * 1536 + c4 * 4];
        *(float4*)&ks[m][c4 * 4] = *(const float4*)&base[(long long)m * 1536 + 512 + c4 * 4];
    }
    __syncthreads();

    int tx = tid & 15, ty = tid >> 4;   // tx->k(4), ty->q(4)
    float dots[4][4];
#pragma unroll
    for (int i = 0; i < 4; i++)
#pragma unroll
        for (int j = 0; j < 4; j++) dots[i][j] = 0.f;
#pragma unroll
    for (int d = 0; d < 64; d += 4) {
        float4 ra[4], rb[4];
#pragma unroll
        for (int i = 0; i < 4; i++) ra[i] = *(float4*)&qs[ty * 4 + i][d];
#pragma unroll
        for (int j = 0; j < 4; j++) rb[j] = *(float4*)&ks[tx * 4 + j][d];
#pragma unroll
        for (int i = 0; i < 4; i++)
#pragma unroll
            for (int j = 0; j < 4; j++)
                dots[i][j] += ra[i].x * rb[j].x + ra[i].y * rb[j].y +
                              ra[i].z * rb[j].z + ra[i].w * rb[j].w;
    }
    __syncthreads();
    // overwrite qs with scaled dots; load v into ks
#pragma unroll
    for (int i = 0; i < 4; i++)
#pragma unroll
        for (int j = 0; j < 4; j++)
            qs[ty * 4 + i][tx * 4 + j] = dots[i][j] * 0.125f;   // 64^-0.5
#pragma unroll
    for (int i = 0; i < 4; i++) {
        int idx = tid + i * 256;
        int m = idx >> 4, c4 = idx & 15;
        *(float4*)&ks[m][c4 * 4] = *(const float4*)&base[(long long)m * 1536 + 1024 + c4 * 4];
    }
    __syncthreads();

    // softmax over k for each row (8 warps x 8 rows)
    int wid = tid >> 5, lane = tid & 31;
#pragma unroll
    for (int r = 0; r < 8; r++) {
        int m = wid * 8 + r;
        float a0 = qs[m][lane], a1 = qs[m][lane + 32];
        float mx = fmaxf(a0, a1);
#pragma unroll
        for (int o = 16; o; o >>= 1) mx = fmaxf(mx, __shfl_xor_sync(0xffffffffu, mx, o));
        float e0 = __expf(a0 - mx), e1 = __expf(a1 - mx);
        float s = e0 + e1;
#pragma unroll
        for (int o = 16; o; o >>= 1) s += __shfl_xor_sync(0xffffffffu, s, o);
        float inv = 1.0f / s;
        qs[m][lane] = e0 * inv; qs[m][lane + 32] = e1 * inv;
    }
    __syncthreads();

    // out = attn @ v ; tx->d(4), ty->q(4)
    float acc[4][4];
#pragma unroll
    for (int i = 0; i < 4; i++)
#pragma unroll
        for (int j = 0; j < 4; j++) acc[i][j] = 0.f;
#pragma unroll 4
    for (int k = 0; k < 64; k++) {
        float rm[4];
#pragma unroll
        for (int i = 0; i < 4; i++) rm[i] = qs[ty * 4 + i][k];
        float4 rv = *(float4*)&ks[k][tx * 4];
#pragma unroll
        for (int i = 0; i < 4; i++) {
            acc[i][0] += rm[i] * rv.x; acc[i][1] += rm[i] * rv.y;
            acc[i][2] += rm[i] * rv.z; acc[i][3] += rm[i] * rv.w;
        }
    }
    float* op = otok + (long long)bh * 4096;
#pragma unroll
    for (int i = 0; i < 4; i++) {
        float4 v = {acc[i][0], acc[i][1], acc[i][2], acc[i][3]};
        *(float4*)&op[(ty * 4 + i) * 64 + tx * 4] = v;
    }
}

// ---------------- scatter: pre[b,n,h*64+d] = sum_m otok[b,h,m,d] * slice_w[b,h*64+m,n] ----------------
__global__ __launch_bounds__(256)
void scatter_kernel(const float* __restrict__ sw, const float* __restrict__ otok,
                    float* __restrict__ pre)
{
    int bh = blockIdx.y; int b = bh >> 3, h = bh & 7;
    int n0 = blockIdx.x * 64;
    __shared__ float sws[64][68];   // [m][n]
    __shared__ float ots[64][64];   // [m][d]
    int tid = threadIdx.x;

    const float* swb = sw + ((long long)b * 512 + h * 64) * NN;
#pragma unroll
    for (int i = 0; i < 4; i++) {
        int idx = tid + i * 256;
        int m = idx >> 4, c4 = idx & 15;
        *(float4*)&sws[m][c4 * 4] = *(const float4*)&swb[(long long)m * NN + n0 + c4 * 4];
        *(float4*)&ots[m][c4 * 4] = *(const float4*)&otok[(long long)bh * 4096 + m * 64 + c4 * 4];
    }
    __syncthreads();

    int tx = tid & 15, ty = tid >> 4;   // tx->d(4), ty->n(4)
    float acc[4][4];
#pragma unroll
    for (int i = 0; i < 4; i++)
#pragma unroll
        for (int j = 0; j < 4; j++) acc[i][j] = 0.f;
#pragma unroll 4
    for (int m = 0; m < 64; m++) {
        float rn[4];
#pragma unroll
        for (int i = 0; i < 4; i++) rn[i] = sws[m][ty * 4 + i];
        float4 rd = *(float4*)&ots[m][tx * 4];
#pragma unroll
        for (int i = 0; i < 4; i++) {
            acc[i][0] += rn[i] * rd.x; acc[i][1] += rn[i] * rd.y;
            acc[i][2] += rn[i] * rd.z; acc[i][3] += rn[i] * rd.w;
        }
    }
    float* pb = pre + (long long)b * NN * 512 + h * 64;
#pragma unroll
    for (int i = 0; i < 4; i++) {
        long long n = n0 + ty * 4 + i;
        float4 v = {acc[i][0], acc[i][1], acc[i][2], acc[i][3]};
        *(float4*)&pb[n * 512 + tx * 4] = v;
    }
}

// ---------------- launch ----------------
extern "C" void kernel_launch(void* const* d_in, const int* in_sizes, int n_in,
                              void* d_out, int out_size)
{
    (void)in_sizes; (void)n_in; (void)out_size;
    const float* x     = (const float*)d_in[0];
    const float* W_kv  = (const float*)d_in[1];
    const float* b_kv  = (const float*)d_in[2];
    const float* wtq   = (const float*)d_in[3];
    const float* W_mix = (const float*)d_in[4];
    const float* ln_g  = (const float*)d_in[5];
    const float* ln_b  = (const float*)d_in[6];
    const float* W_qkv = (const float*)d_in[7];
    const float* W_out = (const float*)d_in[8];
    const float* b_out = (const float*)d_in[9];
    float* out = (float*)d_out;

    float *kv, *scores, *mixed, *sumw, *part, *stok, *st, *qkv, *otok, *pre;
    cudaGetSymbolAddress((void**)&kv, g_kv);
    cudaGetSymbolAddress((void**)&scores, g_scores);
    cudaGetSymbolAddress((void**)&mixed, g_mixed);
    cudaGetSymbolAddress((void**)&sumw, g_sumw);
    cudaGetSymbolAddress((void**)&part, g_part);
    cudaGetSymbolAddress((void**)&stok, g_stok);
    cudaGetSymbolAddress((void**)&st, g_st);
    cudaGetSymbolAddress((void**)&qkv, g_qkv);
    cudaGetSymbolAddress((void**)&otok, g_otok);
    cudaGetSymbolAddress((void**)&pre, g_pre);

    // 1) kv = x @ W_kv + b_kv              [65536,512] x [512,1024]
    sgemm_kernel<<<dim3(1024 / 128, 65536 / 128, 1), 256>>>(
        x, W_kv, b_kv, kv, 65536, 1024, 512, 0, 0, 0);

    // 2) scores = wtq . xk                 per (b,h): [64,64] x [64,8192]
    scores_kernel<<<dim3(NN / 64, 64), 256>>>(kv, wtq, scores);

    // 3) mixed = W_mix @ scores            per b: [512,512] x [512,8192]
    sgemm_kernel<<<dim3(NN / 128, 512 / 128, BB), 256>>>(
        W_mix, scores, nullptr, mixed, 512, NN, 512,
        0, (long long)512 * NN, (long long)512 * NN);

    // 4) softmax over m (in place -> slice_w)
    softmax_kernel<<<dim3(NN / 256, 64), 256>>>(mixed);

    // 4b) sumw over n
    sumw_kernel<<<4096, 256>>>(mixed, sumw);

    // 5) slice_tok = slice_w @ xv (deterministic split-K)
    stok_part_kernel<<<dim3(16, 64), 256>>>(mixed, kv, part);
    stok_reduce_kernel<<<64, 256>>>(part, stok);

    // 6) normalize + layernorm -> st[B,M,D]
    ln_kernel<<<512, 256>>>(stok, sumw, ln_g, ln_b, st);

    // 7) qkv = st @ W_qkv                  [512,512] x [512,1536]
    sgemm_kernel<<<dim3(1536 / 128, 512 / 128, 1), 256>>>(
        st, W_qkv, nullptr, qkv, 512, 1536, 512, 0, 0, 0);

    // 8) mini self-attention over M
    attn_kernel<<<64, 256>>>(qkv, otok);

    // 9) scatter: pre = otok^T applied through slice_w
    scatter_kernel<<<dim3(NN / 64, 64), 256>>>(mixed, otok, pre);

    // 10) out = pre @ W_out + b_out        [65536,512] x [512,512]
    sgemm_kernel<<<dim3(512 / 128, 65536 / 128, 1), 256>>>(
        pre, W_out, b_out, out, 65536, 512, 512, 0, 0, 0);
}